// round 3
// baseline (speedup 1.0000x reference)
#include <cuda_runtime.h>
#include <cuda_bf16.h>

// ---------------------------------------------------------------------------
// TransformerBlock: B=8, T=1024, E=1024, H=16, HD=64, HID=4096, fp32.
// R1 baseline: plain fp32 smem-tiled GEMMs + separate LN/softmax kernels.
// Scratch via __device__ globals (no allocation allowed).
// ---------------------------------------------------------------------------

#define RROWS 8192      // B*T
#define EDIM  1024
#define HEADS 16
#define HD    64
#define HID   4096
#define TSEQ  1024

__device__ float g_xn   [RROWS * EDIM];          // 32 MB  (LN output, reused)
__device__ float g_qkv  [RROWS * 3 * EDIM];      // 96 MB
__device__ float g_sc   [128ll * TSEQ * TSEQ];   // 512 MB (attention scores)
__device__ float g_ycat [RROWS * EDIM];          // 32 MB  (attn out, head-concat)
__device__ float g_h    [RROWS * HID];           // 128 MB (MLP hidden, post-GELU)

__device__ __forceinline__ float gelu_tanh(float x) {
    // matches jax.nn.gelu(approximate=True)
    float x3 = x * x * x;
    return 0.5f * x * (1.0f + tanhf(0.7978845608028654f * (x + 0.044715f * x3)));
}

// ---------------------------------------------------------------------------
// LayerNorm: one block (256 threads) per row of 1024. Two-pass for accuracy.
// ---------------------------------------------------------------------------
__global__ void ln_kernel(const float* __restrict__ x,
                          const float* __restrict__ g,
                          const float* __restrict__ b,
                          float* __restrict__ out) {
    __shared__ float red[8];
    const long long row = blockIdx.x;
    const int t = threadIdx.x;
    float4 v = ((const float4*)(x + row * EDIM))[t];

    float s = v.x + v.y + v.z + v.w;
    #pragma unroll
    for (int o = 16; o; o >>= 1) s += __shfl_xor_sync(~0u, s, o);
    if ((t & 31) == 0) red[t >> 5] = s;
    __syncthreads();
    if (t < 8) {
        s = red[t];
        #pragma unroll
        for (int o = 4; o; o >>= 1) s += __shfl_xor_sync(0xffu, s, o);
        if (t == 0) red[0] = s;
    }
    __syncthreads();
    const float mean = red[0] * (1.0f / EDIM);

    float dx = v.x - mean, dy = v.y - mean, dz = v.z - mean, dw = v.w - mean;
    float q = dx * dx + dy * dy + dz * dz + dw * dw;
    #pragma unroll
    for (int o = 16; o; o >>= 1) q += __shfl_xor_sync(~0u, q, o);
    __syncthreads();                 // everyone is done reading red[0]
    if ((t & 31) == 0) red[t >> 5] = q;
    __syncthreads();
    if (t < 8) {
        q = red[t];
        #pragma unroll
        for (int o = 4; o; o >>= 1) q += __shfl_xor_sync(0xffu, q, o);
        if (t == 0) red[0] = q;
    }
    __syncthreads();
    const float rstd = rsqrtf(red[0] * (1.0f / EDIM) + 1e-5f);

    const float4 gg = ((const float4*)g)[t];
    const float4 bb = ((const float4*)b)[t];
    float4 o4;
    o4.x = dx * rstd * gg.x + bb.x;
    o4.y = dy * rstd * gg.y + bb.y;
    o4.z = dz * rstd * gg.z + bb.z;
    o4.w = dw * rstd * gg.w + bb.w;
    ((float4*)(out + row * EDIM))[t] = o4;
}

// ---------------------------------------------------------------------------
// Row softmax over 1024 cols; one block (256 threads) per row, in-place.
// ---------------------------------------------------------------------------
__global__ void softmax_kernel(float* __restrict__ s) {
    __shared__ float red[8];
    const long long row = blockIdx.x;
    const int t = threadIdx.x;
    float4* p = (float4*)(s + row * (long long)TSEQ);
    float4 v = p[t];

    float m = fmaxf(fmaxf(v.x, v.y), fmaxf(v.z, v.w));
    #pragma unroll
    for (int o = 16; o; o >>= 1) m = fmaxf(m, __shfl_xor_sync(~0u, m, o));
    if ((t & 31) == 0) red[t >> 5] = m;
    __syncthreads();
    if (t < 8) {
        m = red[t];
        #pragma unroll
        for (int o = 4; o; o >>= 1) m = fmaxf(m, __shfl_xor_sync(0xffu, m, o));
        if (t == 0) red[0] = m;
    }
    __syncthreads();
    m = red[0];

    v.x = __expf(v.x - m);
    v.y = __expf(v.y - m);
    v.z = __expf(v.z - m);
    v.w = __expf(v.w - m);
    float q = v.x + v.y + v.z + v.w;
    #pragma unroll
    for (int o = 16; o; o >>= 1) q += __shfl_xor_sync(~0u, q, o);
    __syncthreads();
    if ((t & 31) == 0) red[t >> 5] = q;
    __syncthreads();
    if (t < 8) {
        q = red[t];
        #pragma unroll
        for (int o = 4; o; o >>= 1) q += __shfl_xor_sync(0xffu, q, o);
        if (t == 0) red[0] = q;
    }
    __syncthreads();
    const float inv = 1.0f / red[0];
    v.x *= inv; v.y *= inv; v.z *= inv; v.w *= inv;
    p[t] = v;
}

// ---------------------------------------------------------------------------
// Generic smem-tiled fp32 GEMM.
//   C[m,n] = epilogue( alpha * sum_k A[m,k] * Bop[k,n] )
//   TRANSB=false: Bop[k,n] = B[k*ldb + n]   (B row-major [K,N])
//   TRANSB=true : Bop[k,n] = B[n*ldb + k]   (B row-major [N,K], used transposed)
// Batch via blockIdx.z: per-operand offset = (z/16)*s?b + (z%16)*s?h.
// EPI: 0 none, 1 +bias, 2 +bias then GELU, 3 +bias then +residual (ld=ldc).
// All dims must be multiples of the tile sizes (true for this problem).
// ---------------------------------------------------------------------------
template <int BM, int BN, int BK, int TM, int TN, bool TRANSB, int EPI>
__global__ void gemm_kernel(int K,
                            const float* __restrict__ A, int lda, long long sAb, long long sAh,
                            const float* __restrict__ B, int ldb, long long sBb, long long sBh,
                            float* __restrict__ C, int ldc, long long sCb, long long sCh,
                            const float* __restrict__ bias,
                            const float* __restrict__ res,
                            float alpha) {
    constexpr int THREADS = (BM / TM) * (BN / TN);
    __shared__ float As[BK][BM];
    __shared__ float Bs[BK][BN];

    const int z  = blockIdx.z;
    const int zb = z >> 4, zh = z & 15;
    A += zb * sAb + zh * sAh;
    B += zb * sBb + zh * sBh;
    C += zb * sCb + zh * sCh;
    if (EPI == 3) res += zb * sCb + zh * sCh;   // residual shares C layout here

    const int m0 = blockIdx.y * BM;
    const int n0 = blockIdx.x * BN;
    const int tid = threadIdx.x;
    const int tcol = tid % (BN / TN);
    const int trow = tid / (BN / TN);

    float acc[TM][TN];
    #pragma unroll
    for (int i = 0; i < TM; i++)
        #pragma unroll
        for (int j = 0; j < TN; j++) acc[i][j] = 0.0f;

    for (int k0 = 0; k0 < K; k0 += BK) {
        #pragma unroll
        for (int i = tid; i < BM * BK; i += THREADS) {
            int r = i / BK, c = i % BK;
            As[c][r] = A[(long long)(m0 + r) * lda + (k0 + c)];
        }
        if (!TRANSB) {
            #pragma unroll
            for (int i = tid; i < BK * BN; i += THREADS) {
                int r = i / BN, c = i % BN;
                Bs[r][c] = B[(long long)(k0 + r) * ldb + (n0 + c)];
            }
        } else {
            #pragma unroll
            for (int i = tid; i < BK * BN; i += THREADS) {
                int r = i / BK, c = i % BK;   // r: N index, c: K index
                Bs[c][r] = B[(long long)(n0 + r) * ldb + (k0 + c)];
            }
        }
        __syncthreads();

        #pragma unroll
        for (int kk = 0; kk < BK; kk++) {
            float a[TM], bb[TN];
            #pragma unroll
            for (int i = 0; i < TM; i++) a[i] = As[kk][trow * TM + i];
            #pragma unroll
            for (int j = 0; j < TN; j++) bb[j] = Bs[kk][tcol * TN + j];
            #pragma unroll
            for (int i = 0; i < TM; i++)
                #pragma unroll
                for (int j = 0; j < TN; j++) acc[i][j] += a[i] * bb[j];
        }
        __syncthreads();
    }

    const int mbase = m0 + trow * TM;
    const int nbase = n0 + tcol * TN;
    #pragma unroll
    for (int i = 0; i < TM; i++) {
        #pragma unroll
        for (int j = 0; j < TN; j++) {
            float v = acc[i][j] * alpha;
            if (EPI >= 1) v += bias[nbase + j];
            if (EPI == 2) v = gelu_tanh(v);
            if (EPI == 3) v += res[(long long)(mbase + i) * ldc + (nbase + j)];
            C[(long long)(mbase + i) * ldc + (nbase + j)] = v;
        }
    }
}

// ---------------------------------------------------------------------------
extern "C" void kernel_launch(void* const* d_in, const int* in_sizes, int n_in,
                              void* d_out, int out_size) {
    const float* x     = (const float*)d_in[0];
    const float* ln1g  = (const float*)d_in[1];
    const float* ln1b  = (const float*)d_in[2];
    const float* Wqkv  = (const float*)d_in[3];
    const float* bqkv  = (const float*)d_in[4];
    const float* Wproj = (const float*)d_in[5];
    const float* bproj = (const float*)d_in[6];
    const float* ln2g  = (const float*)d_in[7];
    const float* ln2b  = (const float*)d_in[8];
    const float* Wfc   = (const float*)d_in[9];
    const float* bfc   = (const float*)d_in[10];
    const float* Wout  = (const float*)d_in[11];
    const float* bout  = (const float*)d_in[12];
    float* out = (float*)d_out;

    float *xn, *qkv, *sc, *ycat, *hbuf;
    cudaGetSymbolAddress((void**)&xn,   g_xn);
    cudaGetSymbolAddress((void**)&qkv,  g_qkv);
    cudaGetSymbolAddress((void**)&sc,   g_sc);
    cudaGetSymbolAddress((void**)&ycat, g_ycat);
    cudaGetSymbolAddress((void**)&hbuf, g_h);

    const long long sQKVb = (long long)TSEQ * 3 * EDIM;   // per-batch stride in qkv
    const long long sSCb  = (long long)HEADS * TSEQ * TSEQ;
    const long long sSCh  = (long long)TSEQ * TSEQ;

    // 1) LN1
    ln_kernel<<<RROWS, 256>>>(x, ln1g, ln1b, xn);

    // 2) QKV = xn @ Wqkv + bqkv           [8192,1024]x[1024,3072]
    gemm_kernel<128,128,8,8,8,false,1><<<dim3(3*EDIM/128, RROWS/128, 1), 256>>>(
        EDIM, xn, EDIM, 0, 0, Wqkv, 3*EDIM, 0, 0, qkv, 3*EDIM, 0, 0,
        bqkv, nullptr, 1.0f);

    // 3) scores[b,h] = Q K^T / 8          batched [1024,64]x[64,1024]
    gemm_kernel<128,128,8,8,8,true,0><<<dim3(TSEQ/128, TSEQ/128, 128), 256>>>(
        HD,
        qkv,        3*EDIM, sQKVb, HD,          // Q  (col offset h*64)
        qkv + EDIM, 3*EDIM, sQKVb, HD,          // K
        sc, TSEQ, sSCb, sSCh,
        nullptr, nullptr, 0.125f);

    // 4) softmax over keys
    softmax_kernel<<<128 * TSEQ, 256>>>(sc);

    // 5) ycat[b*T+t, h*64+d] = P @ V      batched [1024,1024]x[1024,64]
    gemm_kernel<128,64,8,8,4,false,0><<<dim3(1, TSEQ/128, 128), 256>>>(
        TSEQ,
        sc, TSEQ, sSCb, sSCh,
        qkv + 2*EDIM, 3*EDIM, sQKVb, HD,        // V
        ycat, EDIM, (long long)TSEQ * EDIM, HD,
        nullptr, nullptr, 1.0f);

    // 6) x1 = x + ycat @ Wproj + bproj    -> d_out
    gemm_kernel<128,128,8,8,8,false,3><<<dim3(EDIM/128, RROWS/128, 1), 256>>>(
        EDIM, ycat, EDIM, 0, 0, Wproj, EDIM, 0, 0, out, EDIM, 0, 0,
        bproj, x, 1.0f);

    // 7) LN2(x1) -> xn
    ln_kernel<<<RROWS, 256>>>(out, ln2g, ln2b, xn);

    // 8) h = gelu(xn @ Wfc + bfc)         [8192,1024]x[1024,4096]
    gemm_kernel<128,128,8,8,8,false,2><<<dim3(HID/128, RROWS/128, 1), 256>>>(
        EDIM, xn, EDIM, 0, 0, Wfc, HID, 0, 0, hbuf, HID, 0, 0,
        bfc, nullptr, 1.0f);

    // 9) out = x1 + h @ Wout + bout       [8192,4096]x[4096,1024] (in-place residual)
    gemm_kernel<128,128,8,8,8,false,3><<<dim3(EDIM/128, RROWS/128, 1), 256>>>(
        HID, hbuf, HID, 0, 0, Wout, EDIM, 0, 0, out, EDIM, 0, 0,
        bout, out, 1.0f);
}

// round 4
// speedup vs baseline: 4.3344x; 4.3344x over previous
#include <cuda_runtime.h>
#include <cuda_bf16.h>
#include <cstdint>

// ---------------------------------------------------------------------------
// TransformerBlock: B=8, T=1024, E=1024, H=16, HD=64, HID=4096, fp32.
// R3: all GEMMs on tensor pipe via mma.sync.m16n8k8 TF32, cp.async double
// buffering. LN/softmax unchanged from R1.
// ---------------------------------------------------------------------------

#define RROWS 8192      // B*T
#define EDIM  1024
#define HEADS 16
#define HD    64
#define HID   4096
#define TSEQ  1024

__device__ float g_xn   [RROWS * EDIM];          // 32 MB  (LN output, reused)
__device__ float g_qkv  [RROWS * 3 * EDIM];      // 96 MB
__device__ float g_sc   [128ll * TSEQ * TSEQ];   // 512 MB (attention scores)
__device__ float g_ycat [RROWS * EDIM];          // 32 MB  (attn out, head-concat)
__device__ float g_h    [RROWS * HID];           // 128 MB (MLP hidden, post-GELU)

__device__ __forceinline__ float gelu_tanh(float x) {
    float x3 = x * x * x;
    return 0.5f * x * (1.0f + tanhf(0.7978845608028654f * (x + 0.044715f * x3)));
}

__device__ __forceinline__ uint32_t f2tf32(float x) {
    uint32_t r;
    asm("cvt.rna.tf32.f32 %0, %1;" : "=r"(r) : "f"(x));
    return r;
}

__device__ __forceinline__ void cp_async16(void* smem_dst, const void* gsrc) {
    uint32_t d = (uint32_t)__cvta_generic_to_shared(smem_dst);
    asm volatile("cp.async.cg.shared.global [%0], [%1], 16;\n" :: "r"(d), "l"(gsrc));
}
__device__ __forceinline__ void cp_commit() {
    asm volatile("cp.async.commit_group;\n");
}
template <int N>
__device__ __forceinline__ void cp_wait() {
    asm volatile("cp.async.wait_group %0;\n" :: "n"(N));
}

__device__ __forceinline__ void mma_tf32(float* c, const uint32_t* a, const uint32_t* b) {
    asm volatile(
        "mma.sync.aligned.m16n8k8.row.col.f32.tf32.tf32.f32 "
        "{%0,%1,%2,%3}, {%4,%5,%6,%7}, {%8,%9}, {%0,%1,%2,%3};"
        : "+f"(c[0]), "+f"(c[1]), "+f"(c[2]), "+f"(c[3])
        : "r"(a[0]), "r"(a[1]), "r"(a[2]), "r"(a[3]), "r"(b[0]), "r"(b[1]));
}

// ---------------------------------------------------------------------------
// LayerNorm: one block (256 threads) per row of 1024.
// ---------------------------------------------------------------------------
__global__ void ln_kernel(const float* __restrict__ x,
                          const float* __restrict__ g,
                          const float* __restrict__ b,
                          float* __restrict__ out) {
    __shared__ float red[8];
    const long long row = blockIdx.x;
    const int t = threadIdx.x;
    float4 v = ((const float4*)(x + row * EDIM))[t];

    float s = v.x + v.y + v.z + v.w;
    #pragma unroll
    for (int o = 16; o; o >>= 1) s += __shfl_xor_sync(~0u, s, o);
    if ((t & 31) == 0) red[t >> 5] = s;
    __syncthreads();
    if (t < 8) {
        s = red[t];
        #pragma unroll
        for (int o = 4; o; o >>= 1) s += __shfl_xor_sync(0xffu, s, o);
        if (t == 0) red[0] = s;
    }
    __syncthreads();
    const float mean = red[0] * (1.0f / EDIM);

    float dx = v.x - mean, dy = v.y - mean, dz = v.z - mean, dw = v.w - mean;
    float q = dx * dx + dy * dy + dz * dz + dw * dw;
    #pragma unroll
    for (int o = 16; o; o >>= 1) q += __shfl_xor_sync(~0u, q, o);
    __syncthreads();
    if ((t & 31) == 0) red[t >> 5] = q;
    __syncthreads();
    if (t < 8) {
        q = red[t];
        #pragma unroll
        for (int o = 4; o; o >>= 1) q += __shfl_xor_sync(0xffu, q, o);
        if (t == 0) red[0] = q;
    }
    __syncthreads();
    const float rstd = rsqrtf(red[0] * (1.0f / EDIM) + 1e-5f);

    const float4 gg = ((const float4*)g)[t];
    const float4 bb = ((const float4*)b)[t];
    float4 o4;
    o4.x = dx * rstd * gg.x + bb.x;
    o4.y = dy * rstd * gg.y + bb.y;
    o4.z = dz * rstd * gg.z + bb.z;
    o4.w = dw * rstd * gg.w + bb.w;
    ((float4*)(out + row * EDIM))[t] = o4;
}

// ---------------------------------------------------------------------------
// Row softmax over 1024 cols; one block (256 threads) per row, in-place.
// ---------------------------------------------------------------------------
__global__ void softmax_kernel(float* __restrict__ s) {
    __shared__ float red[8];
    const long long row = blockIdx.x;
    const int t = threadIdx.x;
    float4* p = (float4*)(s + row * (long long)TSEQ);
    float4 v = p[t];

    float m = fmaxf(fmaxf(v.x, v.y), fmaxf(v.z, v.w));
    #pragma unroll
    for (int o = 16; o; o >>= 1) m = fmaxf(m, __shfl_xor_sync(~0u, m, o));
    if ((t & 31) == 0) red[t >> 5] = m;
    __syncthreads();
    if (t < 8) {
        m = red[t];
        #pragma unroll
        for (int o = 4; o; o >>= 1) m = fmaxf(m, __shfl_xor_sync(0xffu, m, o));
        if (t == 0) red[0] = m;
    }
    __syncthreads();
    m = red[0];

    v.x = __expf(v.x - m);
    v.y = __expf(v.y - m);
    v.z = __expf(v.z - m);
    v.w = __expf(v.w - m);
    float q = v.x + v.y + v.z + v.w;
    #pragma unroll
    for (int o = 16; o; o >>= 1) q += __shfl_xor_sync(~0u, q, o);
    __syncthreads();
    if ((t & 31) == 0) red[t >> 5] = q;
    __syncthreads();
    if (t < 8) {
        q = red[t];
        #pragma unroll
        for (int o = 4; o; o >>= 1) q += __shfl_xor_sync(0xffu, q, o);
        if (t == 0) red[0] = q;
    }
    __syncthreads();
    const float inv = 1.0f / red[0];
    v.x *= inv; v.y *= inv; v.z *= inv; v.w *= inv;
    p[t] = v;
}

// ---------------------------------------------------------------------------
// TF32 tensor-core GEMM, double-buffered cp.async.
//   C[m,n] = epilogue( alpha * sum_k A[m,k] * Bop[k,n] )
//   TRANSB=false: Bop[k,n] = B[k*ldb + n]   (cp.async path)
//   TRANSB=true : Bop[k,n] = B[n*ldb + k]   (scalar transposing load)
// Batch via blockIdx.z: offset = (z>>4)*s?b + (z&15)*s?h.
// EPI: 0 none, 1 +bias, 2 +bias,GELU, 3 +bias,+residual(res, stride ldc).
// Dims must divide tiles (true here). 8 warps, 256 threads.
// ---------------------------------------------------------------------------
template <int BM, int BN, int BK, int WM, int WN, bool TRANSB, int EPI>
__global__ void __launch_bounds__(256)
mma_gemm(int K,
         const float* __restrict__ A, int lda, long long sAb, long long sAh,
         const float* __restrict__ B, int ldb, long long sBb, long long sBh,
         float* __restrict__ C, int ldc, long long sCb, long long sCh,
         const float* __restrict__ bias,
         const float* __restrict__ res,
         float alpha) {
    constexpr int THREADS = (BM / WM) * (BN / WN) * 32;
    static_assert(THREADS == 256, "tile/warp mismatch");
    constexpr int ASTR = BK + 4;       // bank-conflict-free A frag loads
    constexpr int BSTR = BN + 8;       // bank-conflict-free B frag loads
    constexpr int NWN = BN / WN;       // warps along n
    constexpr int MF = WM / 16;        // m fragments per warp
    constexpr int NF = WN / 8;         // n fragments per warp

    __shared__ float As[2][BM * ASTR];
    __shared__ float Bs[2][BK * BSTR];

    const int z  = blockIdx.z;
    const int zb = z >> 4, zh = z & 15;
    A += zb * sAb + zh * sAh;
    B += zb * sBb + zh * sBh;
    C += zb * sCb + zh * sCh;
    if (EPI == 3) res += zb * sCb + zh * sCh;

    const int m0 = blockIdx.y * BM;
    const int n0 = blockIdx.x * BN;
    const int tid  = threadIdx.x;
    const int lane = tid & 31;
    const int warp = tid >> 5;
    const int wm = (warp / NWN) * WM;
    const int wn = (warp % NWN) * WN;
    const int lr = lane >> 2;   // 0..7
    const int lc = lane & 3;    // 0..3

    float acc[MF][NF][4];
    #pragma unroll
    for (int i = 0; i < MF; i++)
        #pragma unroll
        for (int j = 0; j < NF; j++)
            #pragma unroll
            for (int q = 0; q < 4; q++) acc[i][j][q] = 0.0f;

    const int KT = K / BK;

    // ---- tile loaders ----
    auto load_tile = [&](int kt, int buf) {
        const int k0 = kt * BK;
        // A: BM x BK, 16B chunks along k
        constexpr int ACH = BM * BK / 4;
        #pragma unroll
        for (int i = tid; i < ACH; i += THREADS) {
            int r = i / (BK / 4), kc = (i % (BK / 4)) * 4;
            cp_async16(&As[buf][r * ASTR + kc],
                       A + (long long)(m0 + r) * lda + k0 + kc);
        }
        if (!TRANSB) {
            constexpr int BCH = BK * BN / 4;
            #pragma unroll
            for (int i = tid; i < BCH; i += THREADS) {
                int r = i / (BN / 4), nc = (i % (BN / 4)) * 4;
                cp_async16(&Bs[buf][r * BSTR + nc],
                           B + (long long)(k0 + r) * ldb + n0 + nc);
            }
        } else {
            // Bop[k][n] = B[n][k] : scalar transposing load
            #pragma unroll
            for (int i = tid; i < BK * BN; i += THREADS) {
                int k = i % BK, n = i / BK;
                Bs[buf][k * BSTR + n] = B[(long long)(n0 + n) * ldb + k0 + k];
            }
        }
        cp_commit();
    };

    load_tile(0, 0);

    for (int kt = 0; kt < KT; kt++) {
        const int buf = kt & 1;
        if (kt + 1 < KT) {
            load_tile(kt + 1, buf ^ 1);
            cp_wait<1>();
        } else {
            cp_wait<0>();
        }
        __syncthreads();

        #pragma unroll
        for (int kq = 0; kq < BK; kq += 8) {
            uint32_t afr[MF][4];
            #pragma unroll
            for (int im = 0; im < MF; im++) {
                const float* Ab = &As[buf][(wm + im * 16 + lr) * ASTR + kq + lc];
                afr[im][0] = f2tf32(Ab[0]);
                afr[im][1] = f2tf32(Ab[8 * ASTR]);
                afr[im][2] = f2tf32(Ab[4]);
                afr[im][3] = f2tf32(Ab[8 * ASTR + 4]);
            }
            uint32_t bfr[NF][2];
            #pragma unroll
            for (int jn = 0; jn < NF; jn++) {
                const float* Bb = &Bs[buf][(kq + lc) * BSTR + wn + jn * 8 + lr];
                bfr[jn][0] = f2tf32(Bb[0]);
                bfr[jn][1] = f2tf32(Bb[4 * BSTR]);
            }
            #pragma unroll
            for (int im = 0; im < MF; im++)
                #pragma unroll
                for (int jn = 0; jn < NF; jn++)
                    mma_tf32(acc[im][jn], afr[im], bfr[jn]);
        }
        __syncthreads();
    }

    // ---- epilogue ----
    #pragma unroll
    for (int im = 0; im < MF; im++) {
        const int r0 = m0 + wm + im * 16 + lr;
        #pragma unroll
        for (int jn = 0; jn < NF; jn++) {
            const int cb = n0 + wn + jn * 8 + lc * 2;
            float bv0 = 0.0f, bv1 = 0.0f;
            if (EPI >= 1) { bv0 = bias[cb]; bv1 = bias[cb + 1]; }
            #pragma unroll
            for (int half = 0; half < 2; half++) {
                const int r = r0 + half * 8;
                float v0 = acc[im][jn][half * 2 + 0] * alpha;
                float v1 = acc[im][jn][half * 2 + 1] * alpha;
                if (EPI >= 1) { v0 += bv0; v1 += bv1; }
                if (EPI == 2) { v0 = gelu_tanh(v0); v1 = gelu_tanh(v1); }
                if (EPI == 3) {
                    const float* rp = res + (long long)r * ldc + cb;
                    v0 += rp[0]; v1 += rp[1];
                }
                float* cp = C + (long long)r * ldc + cb;
                cp[0] = v0; cp[1] = v1;
            }
        }
    }
}

// ---------------------------------------------------------------------------
extern "C" void kernel_launch(void* const* d_in, const int* in_sizes, int n_in,
                              void* d_out, int out_size) {
    const float* x     = (const float*)d_in[0];
    const float* ln1g  = (const float*)d_in[1];
    const float* ln1b  = (const float*)d_in[2];
    const float* Wqkv  = (const float*)d_in[3];
    const float* bqkv  = (const float*)d_in[4];
    const float* Wproj = (const float*)d_in[5];
    const float* bproj = (const float*)d_in[6];
    const float* ln2g  = (const float*)d_in[7];
    const float* ln2b  = (const float*)d_in[8];
    const float* Wfc   = (const float*)d_in[9];
    const float* bfc   = (const float*)d_in[10];
    const float* Wout  = (const float*)d_in[11];
    const float* bout  = (const float*)d_in[12];
    float* out = (float*)d_out;

    float *xn, *qkv, *sc, *ycat, *hbuf;
    cudaGetSymbolAddress((void**)&xn,   g_xn);
    cudaGetSymbolAddress((void**)&qkv,  g_qkv);
    cudaGetSymbolAddress((void**)&sc,   g_sc);
    cudaGetSymbolAddress((void**)&ycat, g_ycat);
    cudaGetSymbolAddress((void**)&hbuf, g_h);

    const long long sQKVb = (long long)TSEQ * 3 * EDIM;   // per-batch stride in qkv
    const long long sSCb  = (long long)HEADS * TSEQ * TSEQ;
    const long long sSCh  = (long long)TSEQ * TSEQ;

    // 1) LN1
    ln_kernel<<<RROWS, 256>>>(x, ln1g, ln1b, xn);

    // 2) QKV = xn @ Wqkv + bqkv           [8192,1024]x[1024,3072]
    mma_gemm<128,128,16,32,64,false,1><<<dim3(3*EDIM/128, RROWS/128, 1), 256>>>(
        EDIM, xn, EDIM, 0, 0, Wqkv, 3*EDIM, 0, 0, qkv, 3*EDIM, 0, 0,
        bqkv, nullptr, 1.0f);

    // 3) scores[b,h] = Q K^T / 8          batched [1024,64]x[64,1024]^T
    mma_gemm<128,128,16,32,64,true,0><<<dim3(TSEQ/128, TSEQ/128, 128), 256>>>(
        HD,
        qkv,        3*EDIM, sQKVb, HD,          // Q  (head col offset h*64)
        qkv + EDIM, 3*EDIM, sQKVb, HD,          // K
        sc, TSEQ, sSCb, sSCh,
        nullptr, nullptr, 0.125f);

    // 4) softmax over keys
    softmax_kernel<<<128 * TSEQ, 256>>>(sc);

    // 5) ycat = P @ V                     batched [1024,1024]x[1024,64]
    mma_gemm<128,64,16,32,32,false,0><<<dim3(1, TSEQ/128, 128), 256>>>(
        TSEQ,
        sc, TSEQ, sSCb, sSCh,
        qkv + 2*EDIM, 3*EDIM, sQKVb, HD,        // V
        ycat, EDIM, (long long)TSEQ * EDIM, HD,
        nullptr, nullptr, 1.0f);

    // 6) x1 = x + ycat @ Wproj + bproj    -> d_out
    mma_gemm<128,128,16,32,64,false,3><<<dim3(EDIM/128, RROWS/128, 1), 256>>>(
        EDIM, ycat, EDIM, 0, 0, Wproj, EDIM, 0, 0, out, EDIM, 0, 0,
        bproj, x, 1.0f);

    // 7) LN2(x1) -> xn
    ln_kernel<<<RROWS, 256>>>(out, ln2g, ln2b, xn);

    // 8) h = gelu(xn @ Wfc + bfc)         [8192,1024]x[1024,4096]
    mma_gemm<128,128,16,32,64,false,2><<<dim3(HID/128, RROWS/128, 1), 256>>>(
        EDIM, xn, EDIM, 0, 0, Wfc, HID, 0, 0, hbuf, HID, 0, 0,
        bfc, nullptr, 1.0f);

    // 9) out = x1 + h @ Wout + bout       [8192,4096]x[4096,1024]
    mma_gemm<128,128,16,32,64,false,3><<<dim3(EDIM/128, RROWS/128, 1), 256>>>(
        HID, hbuf, HID, 0, 0, Wout, EDIM, 0, 0, out, EDIM, 0, 0,
        bout, out, 1.0f);
}

// round 5
// speedup vs baseline: 4.4079x; 1.0170x over previous
#include <cuda_runtime.h>
#include <cuda_bf16.h>
#include <cstdint>

// ---------------------------------------------------------------------------
// TransformerBlock B=8,T=1024,E=1024,H=16,HD=64,HID=4096 fp32.
// R4: flash-fused attention (no score buffer) + retuned tf32 mma GEMM
// (256x128x16 tile, 8 warps x (64x64), 3-stage cp.async).
// ---------------------------------------------------------------------------

#define RROWS 8192
#define EDIM  1024
#define HEADS 16
#define HD    64
#define HID   4096
#define TSEQ  1024
#define BATCH 8

__device__ float g_xn  [RROWS * EDIM];      // LN output
__device__ float g_qkv [RROWS * 3 * EDIM];  // fused qkv
__device__ float g_ycat[RROWS * EDIM];      // attention out
__device__ float g_h   [RROWS * HID];       // MLP hidden

__device__ __forceinline__ float gelu_tanh(float x) {
    float x3 = x * x * x;
    return 0.5f * x * (1.0f + tanhf(0.7978845608028654f * (x + 0.044715f * x3)));
}
__device__ __forceinline__ uint32_t f2tf32(float x) {
    uint32_t r;
    asm("cvt.rna.tf32.f32 %0, %1;" : "=r"(r) : "f"(x));
    return r;
}
__device__ __forceinline__ void cp_async16(void* smem_dst, const void* gsrc) {
    uint32_t d = (uint32_t)__cvta_generic_to_shared(smem_dst);
    asm volatile("cp.async.cg.shared.global [%0], [%1], 16;\n" :: "r"(d), "l"(gsrc));
}
__device__ __forceinline__ void cp_commit() { asm volatile("cp.async.commit_group;\n"); }
template <int N>
__device__ __forceinline__ void cp_wait() { asm volatile("cp.async.wait_group %0;\n" :: "n"(N)); }

__device__ __forceinline__ void mma_tf32(float* c, const uint32_t* a, const uint32_t* b) {
    asm volatile(
        "mma.sync.aligned.m16n8k8.row.col.f32.tf32.tf32.f32 "
        "{%0,%1,%2,%3}, {%4,%5,%6,%7}, {%8,%9}, {%0,%1,%2,%3};"
        : "+f"(c[0]), "+f"(c[1]), "+f"(c[2]), "+f"(c[3])
        : "r"(a[0]), "r"(a[1]), "r"(a[2]), "r"(a[3]), "r"(b[0]), "r"(b[1]));
}

// ---------------------------------------------------------------------------
// LayerNorm: one block (256 threads) per 1024-col row.
// ---------------------------------------------------------------------------
__global__ void ln_kernel(const float* __restrict__ x,
                          const float* __restrict__ g,
                          const float* __restrict__ b,
                          float* __restrict__ out) {
    __shared__ float red[8];
    const long long row = blockIdx.x;
    const int t = threadIdx.x;
    float4 v = ((const float4*)(x + row * EDIM))[t];

    float s = v.x + v.y + v.z + v.w;
    #pragma unroll
    for (int o = 16; o; o >>= 1) s += __shfl_xor_sync(~0u, s, o);
    if ((t & 31) == 0) red[t >> 5] = s;
    __syncthreads();
    if (t < 8) {
        s = red[t];
        #pragma unroll
        for (int o = 4; o; o >>= 1) s += __shfl_xor_sync(0xffu, s, o);
        if (t == 0) red[0] = s;
    }
    __syncthreads();
    const float mean = red[0] * (1.0f / EDIM);

    float dx = v.x - mean, dy = v.y - mean, dz = v.z - mean, dw = v.w - mean;
    float q = dx * dx + dy * dy + dz * dz + dw * dw;
    #pragma unroll
    for (int o = 16; o; o >>= 1) q += __shfl_xor_sync(~0u, q, o);
    __syncthreads();
    if ((t & 31) == 0) red[t >> 5] = q;
    __syncthreads();
    if (t < 8) {
        q = red[t];
        #pragma unroll
        for (int o = 4; o; o >>= 1) q += __shfl_xor_sync(0xffu, q, o);
        if (t == 0) red[0] = q;
    }
    __syncthreads();
    const float rstd = rsqrtf(red[0] * (1.0f / EDIM) + 1e-5f);

    const float4 gg = ((const float4*)g)[t];
    const float4 bb = ((const float4*)b)[t];
    float4 o4;
    o4.x = dx * rstd * gg.x + bb.x;
    o4.y = dy * rstd * gg.y + bb.y;
    o4.z = dz * rstd * gg.z + bb.z;
    o4.w = dw * rstd * gg.w + bb.w;
    ((float4*)(out + row * EDIM))[t] = o4;
}

// ---------------------------------------------------------------------------
// Flash attention, non-causal. One CTA = 128 q-rows of one (b,h).
// 4 warps; warp w owns q rows [32w,32w+32). Key tiles of 64, double-buffered
// cp.async. S and O in tf32 mma fragments; P staged through smem (per-warp
// rows only -> __syncwarp suffices between P store and PV frag load).
// ---------------------------------------------------------------------------
#define KSTR 68   // Ksm/Qsm/Psm row stride (floats)
#define VSTR 72   // Vsm row stride
// smem (floats): Qsm[128*68] | Ksm[2][64*68] | Vsm[2][64*72] | Psm[128*68]
#define FL_QOFF 0
#define FL_KOFF (128 * KSTR)
#define FL_VOFF (FL_KOFF + 2 * 64 * KSTR)
#define FL_POFF (FL_VOFF + 2 * 64 * VSTR)
#define FL_SMEM_F (FL_POFF + 128 * KSTR)

__global__ void __launch_bounds__(128)
flash_kernel(const float* __restrict__ qkv, float* __restrict__ ycat) {
    extern __shared__ float sm[];
    float* Qsm = sm + FL_QOFF;
    float* Psm = sm + FL_POFF;

    const int tid  = threadIdx.x;
    const int lane = tid & 31;
    const int warp = tid >> 5;
    const int lr = lane >> 2;
    const int lc = lane & 3;
    const int q0 = blockIdx.x * 128;
    const int h  = blockIdx.y;
    const int b  = blockIdx.z;
    const int wm = warp * 32;

    const float* qkvb = qkv + (long long)b * TSEQ * 3 * EDIM;
    const float* Qg = qkvb + h * HD;
    const float* Kg = qkvb + EDIM + h * HD;
    const float* Vg = qkvb + 2 * EDIM + h * HD;

    // Load Q tile (scaled by 1/sqrt(64)=0.125)
    #pragma unroll
    for (int i = tid; i < 128 * 16; i += 128) {
        int r = i >> 4, c4 = (i & 15) << 2;
        float4 v = *(const float4*)(Qg + (long long)(q0 + r) * 3 * EDIM + c4);
        float* d = Qsm + r * KSTR + c4;
        d[0] = v.x * 0.125f; d[1] = v.y * 0.125f; d[2] = v.z * 0.125f; d[3] = v.w * 0.125f;
    }

    auto load_kv = [&](int j, int buf) {
        float* Ks = sm + FL_KOFF + buf * 64 * KSTR;
        float* Vs = sm + FL_VOFF + buf * 64 * VSTR;
        const float* Kj = Kg + (long long)(j * 64) * 3 * EDIM;
        const float* Vj = Vg + (long long)(j * 64) * 3 * EDIM;
        #pragma unroll
        for (int i = tid; i < 64 * 16; i += 128) {
            int r = i >> 4, c4 = (i & 15) << 2;
            cp_async16(Ks + r * KSTR + c4, Kj + (long long)r * 3 * EDIM + c4);
            cp_async16(Vs + r * VSTR + c4, Vj + (long long)r * 3 * EDIM + c4);
        }
        cp_commit();
    };

    float o[2][8][4];
    float m[2][2], l[2][2];
    #pragma unroll
    for (int im = 0; im < 2; im++) {
        #pragma unroll
        for (int jn = 0; jn < 8; jn++)
            #pragma unroll
            for (int q = 0; q < 4; q++) o[im][jn][q] = 0.0f;
        m[im][0] = m[im][1] = -1e30f;
        l[im][0] = l[im][1] = 0.0f;
    }

    load_kv(0, 0);

    const int NT = TSEQ / 64;
    for (int j = 0; j < NT; j++) {
        const int buf = j & 1;
        if (j + 1 < NT) { load_kv(j + 1, buf ^ 1); cp_wait<1>(); }
        else           { cp_wait<0>(); }
        __syncthreads();

        const float* Ks = sm + FL_KOFF + buf * 64 * KSTR;
        const float* Vs = sm + FL_VOFF + buf * 64 * VSTR;

        // ---- S = Q K^T (rows wm..wm+31, keys 0..63 of tile) ----
        float s[2][8][4];
        #pragma unroll
        for (int im = 0; im < 2; im++)
            #pragma unroll
            for (int jn = 0; jn < 8; jn++)
                #pragma unroll
                for (int q = 0; q < 4; q++) s[im][jn][q] = 0.0f;

        #pragma unroll
        for (int kq = 0; kq < HD; kq += 8) {
            uint32_t afr[2][4];
            #pragma unroll
            for (int im = 0; im < 2; im++) {
                const float* Ab = Qsm + (wm + im * 16 + lr) * KSTR + kq + lc;
                afr[im][0] = f2tf32(Ab[0]);
                afr[im][1] = f2tf32(Ab[8 * KSTR]);
                afr[im][2] = f2tf32(Ab[4]);
                afr[im][3] = f2tf32(Ab[8 * KSTR + 4]);
            }
            #pragma unroll
            for (int jn = 0; jn < 8; jn++) {
                const float* Bb = Ks + (jn * 8 + lr) * KSTR + kq + lc;
                uint32_t bfr[2];
                bfr[0] = f2tf32(Bb[0]);
                bfr[1] = f2tf32(Bb[4]);
                #pragma unroll
                for (int im = 0; im < 2; im++) mma_tf32(s[im][jn], afr[im], bfr);
            }
        }

        // ---- online softmax; write P to smem (own rows only) ----
        #pragma unroll
        for (int im = 0; im < 2; im++) {
            #pragma unroll
            for (int hf = 0; hf < 2; hf++) {
                float mx = -1e30f;
                #pragma unroll
                for (int jn = 0; jn < 8; jn++)
                    mx = fmaxf(mx, fmaxf(s[im][jn][hf * 2], s[im][jn][hf * 2 + 1]));
                mx = fmaxf(mx, __shfl_xor_sync(~0u, mx, 1));
                mx = fmaxf(mx, __shfl_xor_sync(~0u, mx, 2));
                const float mnew = fmaxf(m[im][hf], mx);
                const float alpha = __expf(m[im][hf] - mnew);
                m[im][hf] = mnew;
                const int prow = wm + im * 16 + hf * 8 + lr;
                float sum = 0.0f;
                #pragma unroll
                for (int jn = 0; jn < 8; jn++) {
                    float p0 = __expf(s[im][jn][hf * 2]     - mnew);
                    float p1 = __expf(s[im][jn][hf * 2 + 1] - mnew);
                    sum += p0 + p1;
                    *(float2*)(Psm + prow * KSTR + jn * 8 + 2 * lc) = make_float2(p0, p1);
                }
                sum += __shfl_xor_sync(~0u, sum, 1);
                sum += __shfl_xor_sync(~0u, sum, 2);
                l[im][hf] = l[im][hf] * alpha + sum;
                #pragma unroll
                for (int jn = 0; jn < 8; jn++) {
                    o[im][jn][hf * 2]     *= alpha;
                    o[im][jn][hf * 2 + 1] *= alpha;
                }
            }
        }
        __syncwarp();

        // ---- O += P @ V  (k = 64 keys of tile) ----
        #pragma unroll
        for (int kq = 0; kq < 64; kq += 8) {
            uint32_t afr[2][4];
            #pragma unroll
            for (int im = 0; im < 2; im++) {
                const float* Ab = Psm + (wm + im * 16 + lr) * KSTR + kq + lc;
                afr[im][0] = f2tf32(Ab[0]);
                afr[im][1] = f2tf32(Ab[8 * KSTR]);
                afr[im][2] = f2tf32(Ab[4]);
                afr[im][3] = f2tf32(Ab[8 * KSTR + 4]);
            }
            #pragma unroll
            for (int jn = 0; jn < 8; jn++) {
                const float* Bb = Vs + (kq + lc) * VSTR + jn * 8 + lr;
                uint32_t bfr[2];
                bfr[0] = f2tf32(Bb[0]);
                bfr[1] = f2tf32(Bb[4 * VSTR]);
                #pragma unroll
                for (int im = 0; im < 2; im++) mma_tf32(o[im][jn], afr[im], bfr);
            }
        }
        __syncthreads();
    }

    // ---- write O / l ----
    #pragma unroll
    for (int im = 0; im < 2; im++) {
        #pragma unroll
        for (int hf = 0; hf < 2; hf++) {
            const float inv = 1.0f / l[im][hf];
            const long long row = (long long)b * TSEQ + q0 + wm + im * 16 + hf * 8 + lr;
            #pragma unroll
            for (int jn = 0; jn < 8; jn++) {
                *(float2*)(ycat + row * EDIM + h * HD + jn * 8 + 2 * lc) =
                    make_float2(o[im][jn][hf * 2] * inv, o[im][jn][hf * 2 + 1] * inv);
            }
        }
    }
}

// ---------------------------------------------------------------------------
// TF32 GEMM: 256x128x16 CTA tile, 8 warps x (64x64), 3-stage cp.async.
//   C = epilogue(sum_k A[m,k] * B[k,n]);  EPI: 1 +bias, 2 +bias,GELU,
//   3 +bias,+res (stride ldc). Dims divide tiles; K/16 >= 2.
// ---------------------------------------------------------------------------
#define GBM 256
#define GBN 128
#define GBK 16
#define ASTR 20     // GBK+4
#define BSTR 136    // GBN+8
#define AS_F (GBM * ASTR)   // per-stage floats
#define BS_F (GBK * BSTR)
#define G_SMEM_F (3 * (AS_F + BS_F))

template <int EPI>
__global__ void __launch_bounds__(256)
mma_gemm(int K,
         const float* __restrict__ A, int lda,
         const float* __restrict__ B, int ldb,
         float* __restrict__ C, int ldc,
         const float* __restrict__ bias,
         const float* __restrict__ res) {
    extern __shared__ float sm[];
    const int m0 = blockIdx.y * GBM;
    const int n0 = blockIdx.x * GBN;
    const int tid  = threadIdx.x;
    const int lane = tid & 31;
    const int warp = tid >> 5;
    const int wm = (warp >> 1) * 64;
    const int wn = (warp & 1) * 64;
    const int lr = lane >> 2;
    const int lc = lane & 3;

    float acc[4][8][4];
    #pragma unroll
    for (int i = 0; i < 4; i++)
        #pragma unroll
        for (int j = 0; j < 8; j++)
            #pragma unroll
            for (int q = 0; q < 4; q++) acc[i][j][q] = 0.0f;

    const int KT = K / GBK;

    auto load_tile = [&](int kt, int st) {
        float* As = sm + st * AS_F;
        float* Bs = sm + 3 * AS_F + st * BS_F;
        const int k0 = kt * GBK;
        #pragma unroll
        for (int i = tid; i < GBM * GBK / 4; i += 256) {
            int r = i >> 2, kc = (i & 3) << 2;
            cp_async16(As + r * ASTR + kc, A + (long long)(m0 + r) * lda + k0 + kc);
        }
        #pragma unroll
        for (int i = tid; i < GBK * GBN / 4; i += 256) {
            int r = i >> 5, nc = (i & 31) << 2;
            cp_async16(Bs + r * BSTR + nc, B + (long long)(k0 + r) * ldb + n0 + nc);
        }
        cp_commit();
    };

    load_tile(0, 0);
    load_tile(1, 1);

    int st = 0;
    for (int kt = 0; kt < KT; kt++) {
        cp_wait<1>();
        __syncthreads();
        if (kt + 2 < KT) {
            int st2 = st + 2; if (st2 >= 3) st2 -= 3;
            load_tile(kt + 2, st2);
        }
        const float* As = sm + st * AS_F;
        const float* Bs = sm + 3 * AS_F + st * BS_F;

        #pragma unroll
        for (int kq = 0; kq < GBK; kq += 8) {
            uint32_t afr[4][4];
            #pragma unroll
            for (int im = 0; im < 4; im++) {
                const float* Ab = As + (wm + im * 16 + lr) * ASTR + kq + lc;
                afr[im][0] = f2tf32(Ab[0]);
                afr[im][1] = f2tf32(Ab[8 * ASTR]);
                afr[im][2] = f2tf32(Ab[4]);
                afr[im][3] = f2tf32(Ab[8 * ASTR + 4]);
            }
            #pragma unroll
            for (int jn = 0; jn < 8; jn++) {
                const float* Bb = Bs + (kq + lc) * BSTR + wn + jn * 8 + lr;
                uint32_t bfr[2];
                bfr[0] = f2tf32(Bb[0]);
                bfr[1] = f2tf32(Bb[4 * BSTR]);
                #pragma unroll
                for (int im = 0; im < 4; im++) mma_tf32(acc[im][jn], afr[im], bfr);
            }
        }
        __syncthreads();
        if (++st == 3) st = 0;
    }

    // epilogue
    #pragma unroll
    for (int im = 0; im < 4; im++) {
        const int r0 = m0 + wm + im * 16 + lr;
        #pragma unroll
        for (int jn = 0; jn < 8; jn++) {
            const int cb = n0 + wn + jn * 8 + lc * 2;
            float bv0 = bias[cb], bv1 = bias[cb + 1];
            #pragma unroll
            for (int hf = 0; hf < 2; hf++) {
                const int r = r0 + hf * 8;
                float v0 = acc[im][jn][hf * 2]     + bv0;
                float v1 = acc[im][jn][hf * 2 + 1] + bv1;
                if (EPI == 2) { v0 = gelu_tanh(v0); v1 = gelu_tanh(v1); }
                if (EPI == 3) {
                    const float* rp = res + (long long)r * ldc + cb;
                    v0 += rp[0]; v1 += rp[1];
                }
                float* cp = C + (long long)r * ldc + cb;
                cp[0] = v0; cp[1] = v1;
            }
        }
    }
}

// ---------------------------------------------------------------------------
extern "C" void kernel_launch(void* const* d_in, const int* in_sizes, int n_in,
                              void* d_out, int out_size) {
    const float* x     = (const float*)d_in[0];
    const float* ln1g  = (const float*)d_in[1];
    const float* ln1b  = (const float*)d_in[2];
    const float* Wqkv  = (const float*)d_in[3];
    const float* bqkv  = (const float*)d_in[4];
    const float* Wproj = (const float*)d_in[5];
    const float* bproj = (const float*)d_in[6];
    const float* ln2g  = (const float*)d_in[7];
    const float* ln2b  = (const float*)d_in[8];
    const float* Wfc   = (const float*)d_in[9];
    const float* bfc   = (const float*)d_in[10];
    const float* Wout  = (const float*)d_in[11];
    const float* bout  = (const float*)d_in[12];
    float* out = (float*)d_out;

    float *xn, *qkv, *ycat, *hbuf;
    cudaGetSymbolAddress((void**)&xn,   g_xn);
    cudaGetSymbolAddress((void**)&qkv,  g_qkv);
    cudaGetSymbolAddress((void**)&ycat, g_ycat);
    cudaGetSymbolAddress((void**)&hbuf, g_h);

    const int gsmem = G_SMEM_F * sizeof(float);       // ~87.5 KB
    const int fsmem = FL_SMEM_F * sizeof(float);      // ~138 KB
    static bool attr_done = false;
    if (!attr_done) {
        cudaFuncSetAttribute(mma_gemm<1>, cudaFuncAttributeMaxDynamicSharedMemorySize, gsmem);
        cudaFuncSetAttribute(mma_gemm<2>, cudaFuncAttributeMaxDynamicSharedMemorySize, gsmem);
        cudaFuncSetAttribute(mma_gemm<3>, cudaFuncAttributeMaxDynamicSharedMemorySize, gsmem);
        cudaFuncSetAttribute(flash_kernel, cudaFuncAttributeMaxDynamicSharedMemorySize, fsmem);
        attr_done = true;
    }

    // 1) LN1
    ln_kernel<<<RROWS, 256>>>(x, ln1g, ln1b, xn);

    // 2) QKV = LN1(x) @ Wqkv + bqkv       [8192,1024]x[1024,3072]
    mma_gemm<1><<<dim3(3 * EDIM / GBN, RROWS / GBM), 256, gsmem>>>(
        EDIM, xn, EDIM, Wqkv, 3 * EDIM, qkv, 3 * EDIM, bqkv, nullptr);

    // 3) flash attention -> ycat
    flash_kernel<<<dim3(TSEQ / 128, HEADS, BATCH), 128, fsmem>>>(qkv, ycat);

    // 4) x1 = x + ycat @ Wproj + bproj    -> d_out
    mma_gemm<3><<<dim3(EDIM / GBN, RROWS / GBM), 256, gsmem>>>(
        EDIM, ycat, EDIM, Wproj, EDIM, out, EDIM, bproj, x);

    // 5) LN2(x1) -> xn
    ln_kernel<<<RROWS, 256>>>(out, ln2g, ln2b, xn);

    // 6) h = gelu(xn @ Wfc + bfc)         [8192,1024]x[1024,4096]
    mma_gemm<2><<<dim3(HID / GBN, RROWS / GBM), 256, gsmem>>>(
        EDIM, xn, EDIM, Wfc, HID, hbuf, HID, bfc, nullptr);

    // 7) out = x1 + h @ Wout + bout       [8192,4096]x[4096,1024]
    mma_gemm<3><<<dim3(EDIM / GBN, RROWS / GBM), 256, gsmem>>>(
        HID, hbuf, HID, Wout, EDIM, out, EDIM, bout, out);
}